// round 2
// baseline (speedup 1.0000x reference)
#include <cuda_runtime.h>
#include <math.h>

#define BB 2
#define SS 2048
#define EE 768
#define HH 12
#define DK 64

// Scratch (allocation-free: __device__ globals)
__device__ float g_Q[BB*HH*SS*DK];   // [B,H,S,Dk]
__device__ float g_K[BB*HH*SS*DK];
__device__ float g_V[BB*HH*SS*DK];
__device__ float g_C[BB*SS*EE];      // concat [B,S,H*Dk]

// ---------------------------------------------------------------------------
// Per-head projection GEMM: for (b,h,tile): C[64,64] = X[64x768] * W_h[768x64]
// grid = (S/64, H, B), block = 256
// ---------------------------------------------------------------------------
__global__ __launch_bounds__(256) void proj_kernel(
    const float* __restrict__ X, const float* __restrict__ Wt, int which)
{
    int tile = blockIdx.x, h = blockIdx.y, b = blockIdx.z;
    float* Out = (which == 0) ? g_Q : (which == 1) ? g_K : g_V;

    const float* A  = X  + (size_t)(b*SS + tile*64) * EE;
    const float* Bw = Wt + (size_t)h * EE * DK;
    float*       C  = Out + (size_t)((b*HH + h)*SS + tile*64) * DK;

    __shared__ float As[16][64];   // transposed A tile: As[k][m]
    __shared__ float Bs[16][64];   // Bs[k][n]

    int tid = threadIdx.x;
    int tx = tid & 15, ty = tid >> 4;
    float acc[4][4] = {};

    for (int k0 = 0; k0 < EE; k0 += 16) {
        #pragma unroll
        for (int i = 0; i < 4; i++) {
            int idx = tid + i * 256;
            int m = idx >> 4, kk = idx & 15;
            As[kk][m] = A[m * EE + k0 + kk];
        }
        #pragma unroll
        for (int i = 0; i < 4; i++) {
            int idx = tid + i * 256;
            int kk = idx >> 6, n = idx & 63;
            Bs[kk][n] = Bw[(k0 + kk) * DK + n];
        }
        __syncthreads();
        #pragma unroll
        for (int k = 0; k < 16; k++) {
            float4 a4 = *(const float4*)&As[k][ty * 4];
            float4 b4 = *(const float4*)&Bs[k][tx * 4];
            float av[4] = {a4.x, a4.y, a4.z, a4.w};
            float bv[4] = {b4.x, b4.y, b4.z, b4.w};
            #pragma unroll
            for (int i = 0; i < 4; i++)
                #pragma unroll
                for (int j = 0; j < 4; j++)
                    acc[i][j] += av[i] * bv[j];
        }
        __syncthreads();
    }
    #pragma unroll
    for (int i = 0; i < 4; i++)
        #pragma unroll
        for (int j = 0; j < 4; j++)
            C[(ty*4 + i) * DK + tx*4 + j] = acc[i][j];
}

// ---------------------------------------------------------------------------
// Flash attention with mask. grid = (S/64, H, B), block = 256.
// 4 threads cooperate per query row; each owns 16 of the 64 head dims.
// Q in registers, K/V/mask tiles (32 keys) staged in smem.
// Writes result directly into concat layout g_C[B,S,H*Dk].
// ---------------------------------------------------------------------------
__global__ __launch_bounds__(256) void flash_kernel(const int* __restrict__ mask)
{
    int qt = blockIdx.x, h = blockIdx.y, b = blockIdx.z;
    int tid = threadIdx.x;
    int r   = tid >> 2;       // query row within tile, 0..63
    int sub = tid & 3;        // dim group: owns dims [sub*16, sub*16+16)

    __shared__ float Ks[32][64];
    __shared__ float Vs[32][64];
    __shared__ int   Ms[64][32];

    const float* Qp = g_Q + (size_t)((b*HH + h)*SS + qt*64) * DK;
    const float* Kp = g_K + (size_t)(b*HH + h) * SS * DK;
    const float* Vp = g_V + (size_t)(b*HH + h) * SS * DK;
    const int*   Mp = mask + (size_t)(b*SS + qt*64) * SS;

    // Q row slice into registers (4 float4 = 16 dims)
    float4 q4[4];
    #pragma unroll
    for (int i = 0; i < 4; i++)
        q4[i] = *(const float4*)&Qp[r * DK + sub * 16 + i * 4];

    float m_i = -INFINITY, l_i = 0.f;
    float acc[16];
    #pragma unroll
    for (int d = 0; d < 16; d++) acc[d] = 0.f;

    for (int kt = 0; kt < SS / 32; kt++) {
        __syncthreads();
        // K/V tiles: 2048 floats each, 8 per thread, coalesced
        #pragma unroll
        for (int j = 0; j < 8; j++) {
            int idx = tid + j * 256;
            int i = idx >> 6, c = idx & 63;
            Ks[i][c] = Kp[(kt*32 + i) * DK + c];
            Vs[i][c] = Vp[(kt*32 + i) * DK + c];
        }
        // mask tile: 2048 ints, 8 per thread
        #pragma unroll
        for (int j = 0; j < 8; j++) {
            int idx = tid + j * 256;
            int rr = idx >> 5, cc = idx & 31;
            Ms[rr][cc] = Mp[rr * SS + kt*32 + cc];
        }
        __syncthreads();

        // partial scores over this thread's 16 dims
        float s[32];
        #pragma unroll
        for (int j = 0; j < 32; j++) {
            const float* kr = &Ks[j][sub * 16];
            float4 k0 = *(const float4*)&kr[0];
            float4 k1 = *(const float4*)&kr[4];
            float4 k2 = *(const float4*)&kr[8];
            float4 k3 = *(const float4*)&kr[12];
            float p = q4[0].x*k0.x + q4[0].y*k0.y + q4[0].z*k0.z + q4[0].w*k0.w;
            p += q4[1].x*k1.x + q4[1].y*k1.y + q4[1].z*k1.z + q4[1].w*k1.w;
            p += q4[2].x*k2.x + q4[2].y*k2.y + q4[2].z*k2.z + q4[2].w*k2.w;
            p += q4[3].x*k3.x + q4[3].y*k3.y + q4[3].z*k3.z + q4[3].w*k3.w;
            s[j] = p;
        }
        // butterfly reduce across the 4-thread group -> full dot in all 4
        #pragma unroll
        for (int j = 0; j < 32; j++) {
            s[j] += __shfl_xor_sync(0xffffffffu, s[j], 1);
            s[j] += __shfl_xor_sync(0xffffffffu, s[j], 2);
        }

        // scale + mask, running max (int4 mask reads)
        float mt = m_i;
        #pragma unroll
        for (int j4 = 0; j4 < 8; j4++) {
            int4 mk = *(const int4*)&Ms[r][j4 * 4];
            int j = j4 * 4;
            s[j+0] = mk.x ? s[j+0] * 0.125f : -1e9f;
            s[j+1] = mk.y ? s[j+1] * 0.125f : -1e9f;
            s[j+2] = mk.z ? s[j+2] * 0.125f : -1e9f;
            s[j+3] = mk.w ? s[j+3] * 0.125f : -1e9f;
        }
        #pragma unroll
        for (int j = 0; j < 32; j++) mt = fmaxf(mt, s[j]);

        float corr = __expf(m_i - mt);   // 0 when m_i == -inf
        l_i *= corr;
        #pragma unroll
        for (int d = 0; d < 16; d++) acc[d] *= corr;

        #pragma unroll
        for (int j = 0; j < 32; j++) {
            float p = __expf(s[j] - mt);
            l_i += p;
            const float* vr = &Vs[j][sub * 16];
            #pragma unroll
            for (int d4 = 0; d4 < 4; d4++) {
                float4 v4 = *(const float4*)&vr[d4 * 4];
                acc[d4*4+0] += p * v4.x;
                acc[d4*4+1] += p * v4.y;
                acc[d4*4+2] += p * v4.z;
                acc[d4*4+3] += p * v4.w;
            }
        }
        m_i = mt;
    }

    float inv = 1.f / l_i;
    float* Cp = g_C + (size_t)(b*SS + qt*64 + r) * EE + h * DK + sub * 16;
    #pragma unroll
    for (int d4 = 0; d4 < 4; d4++) {
        float4 o;
        o.x = acc[d4*4+0] * inv;
        o.y = acc[d4*4+1] * inv;
        o.z = acc[d4*4+2] * inv;
        o.w = acc[d4*4+3] * inv;
        *(float4*)&Cp[d4 * 4] = o;
    }
}

// ---------------------------------------------------------------------------
// Output projection: out[4096,768] = g_C[4096,768] @ W[768,768]
// grid = (M/64, N/64) = (64, 12), block = 256
// ---------------------------------------------------------------------------
__global__ __launch_bounds__(256) void out_proj_kernel(
    const float* __restrict__ W, float* __restrict__ outp)
{
    int mt = blockIdx.x, nt = blockIdx.y;
    const float* A = g_C + (size_t)mt * 64 * EE;
    const float* Bw = W + nt * 64;
    float* C = outp + (size_t)mt * 64 * EE + nt * 64;

    __shared__ float As[16][64];
    __shared__ float Bs[16][64];

    int tid = threadIdx.x;
    int tx = tid & 15, ty = tid >> 4;
    float acc[4][4] = {};

    for (int k0 = 0; k0 < EE; k0 += 16) {
        #pragma unroll
        for (int i = 0; i < 4; i++) {
            int idx = tid + i * 256;
            int m = idx >> 4, kk = idx & 15;
            As[kk][m] = A[m * EE + k0 + kk];
        }
        #pragma unroll
        for (int i = 0; i < 4; i++) {
            int idx = tid + i * 256;
            int kk = idx >> 6, n = idx & 63;
            Bs[kk][n] = Bw[(k0 + kk) * EE + n];
        }
        __syncthreads();
        #pragma unroll
        for (int k = 0; k < 16; k++) {
            float4 a4 = *(const float4*)&As[k][ty * 4];
            float4 b4 = *(const float4*)&Bs[k][tx * 4];
            float av[4] = {a4.x, a4.y, a4.z, a4.w};
            float bv[4] = {b4.x, b4.y, b4.z, b4.w};
            #pragma unroll
            for (int i = 0; i < 4; i++)
                #pragma unroll
                for (int j = 0; j < 4; j++)
                    acc[i][j] += av[i] * bv[j];
        }
        __syncthreads();
    }
    #pragma unroll
    for (int i = 0; i < 4; i++)
        #pragma unroll
        for (int j = 0; j < 4; j++)
            C[(ty*4 + i) * EE + tx*4 + j] = acc[i][j];
}

// ---------------------------------------------------------------------------
extern "C" void kernel_launch(void* const* d_in, const int* in_sizes, int n_in,
                              void* d_out, int out_size)
{
    const float* q    = (const float*)d_in[0];
    const float* k    = (const float*)d_in[1];
    const float* v    = (const float*)d_in[2];
    const int*   mask = (const int*)  d_in[3];
    const float* Wq   = (const float*)d_in[4];
    const float* Wk   = (const float*)d_in[5];
    const float* Wv   = (const float*)d_in[6];
    const float* W    = (const float*)d_in[7];
    float* out = (float*)d_out;

    dim3 gp(SS / 64, HH, BB);
    proj_kernel<<<gp, 256>>>(q, Wq, 0);
    proj_kernel<<<gp, 256>>>(k, Wk, 1);
    proj_kernel<<<gp, 256>>>(v, Wv, 2);

    flash_kernel<<<dim3(SS / 64, HH, BB), 256>>>(mask);

    out_proj_kernel<<<dim3((BB * SS) / 64, EE / 64), 256>>>(W, out);
}

// round 5
// speedup vs baseline: 3.6825x; 3.6825x over previous
#include <cuda_runtime.h>
#include <math.h>

#define BB 2
#define SS 2048
#define EE 768
#define HH 12
#define DK 64

// Scratch (allocation-free: __device__ globals)
__device__ float g_Q[BB*HH*SS*DK];   // [B,H,S,Dk]
__device__ float g_K[BB*HH*SS*DK];
__device__ float g_V[BB*HH*SS*DK];
__device__ float g_C[BB*SS*EE];      // concat [B,S,H*Dk]

// Convert f32 -> tf32 (round-to-nearest), kept in a float container.
__device__ __forceinline__ float f2tf(float x) {
    unsigned u;
    asm("cvt.rna.tf32.f32 %0, %1;" : "=r"(u) : "f"(x));
    return __uint_as_float(u);
}

// D += A*B, m16n8k8 tf32, A row-major, B col-major, f32 accumulate.
__device__ __forceinline__ void mma8(float c[4], const unsigned a[4], const unsigned b[2]) {
    asm volatile(
        "mma.sync.aligned.m16n8k8.row.col.f32.tf32.tf32.f32 "
        "{%0,%1,%2,%3},{%4,%5,%6,%7},{%8,%9},{%0,%1,%2,%3};"
        : "+f"(c[0]), "+f"(c[1]), "+f"(c[2]), "+f"(c[3])
        : "r"(a[0]), "r"(a[1]), "r"(a[2]), "r"(a[3]), "r"(b[0]), "r"(b[1]));
}

// ---------------------------------------------------------------------------
// 3xTF32 GEMM, 64x64 block tile, BK=32, 128 threads (4 warps x 16 rows).
// mode 0: QKV projections. grid=(M/64, H, 3).
// mode 1: out projection. grid=(M/64, EE/64, 1).
// ---------------------------------------------------------------------------
__global__ __launch_bounds__(128) void gemm_kernel(
    const float* __restrict__ Xq, const float* __restrict__ Xk, const float* __restrict__ Xv,
    const float* __restrict__ Wq, const float* __restrict__ Wk, const float* __restrict__ Wv,
    const float* __restrict__ Wo, float* __restrict__ outp, int mode)
{
    __shared__ float Ah[64*36], Al[64*36];   // [r][c] at r*36+c
    __shared__ float Bh[32*72], Bl[32*72];   // [e][n] at e*72+n

    int bx = blockIdx.x, hn = blockIdx.y, which = blockIdx.z;
    int t = threadIdx.x, w = t >> 5, l = t & 31;
    int m0 = bx * 64;

    const float* A;
    const float* Bw;
    if (mode == 0) {
        A = (which == 0) ? Xq : (which == 1) ? Xk : Xv;
        const float* Ws = (which == 0) ? Wq : (which == 1) ? Wk : Wv;
        Bw = Ws + (size_t)hn * EE * DK;
    } else {
        A = g_C;
        Bw = Wo + hn * 64;
    }

    float acc[8][4] = {};
    int r0 = 16*w + (l >> 2);   // fragment row base
    int cq = l & 3;             // fragment col base

    for (int k0 = 0; k0 < EE; k0 += 32) {
        __syncthreads();
        #pragma unroll
        for (int i = 0; i < 16; i++) {
            int idx = t + i * 128;
            int r = idx >> 5, c = idx & 31;
            float x = A[(size_t)(m0 + r) * EE + k0 + c];
            float h = f2tf(x);
            Ah[r*36 + c] = h;
            Al[r*36 + c] = f2tf(x - h);
        }
        #pragma unroll
        for (int i = 0; i < 16; i++) {
            int idx = t + i * 128;
            int e = idx >> 6, n = idx & 63;
            float x = (mode == 0) ? Bw[(size_t)(k0 + e) * DK + n]
                                  : Bw[(size_t)(k0 + e) * EE + n];
            float h = f2tf(x);
            Bh[e*72 + n] = h;
            Bl[e*72 + n] = f2tf(x - h);
        }
        __syncthreads();

        #pragma unroll
        for (int kc = 0; kc < 4; kc++) {
            unsigned ah[4], al[4];
            {
                const float* ap = &Ah[r0*36 + kc*8 + cq];
                ah[0] = __float_as_uint(ap[0]);
                ah[1] = __float_as_uint(ap[8*36]);
                ah[2] = __float_as_uint(ap[4]);
                ah[3] = __float_as_uint(ap[8*36 + 4]);
                const float* aq = &Al[r0*36 + kc*8 + cq];
                al[0] = __float_as_uint(aq[0]);
                al[1] = __float_as_uint(aq[8*36]);
                al[2] = __float_as_uint(aq[4]);
                al[3] = __float_as_uint(aq[8*36 + 4]);
            }
            #pragma unroll
            for (int n0 = 0; n0 < 8; n0++) {
                unsigned bh[2], bl2[2];
                const float* bp = &Bh[(kc*8 + cq)*72 + n0*8 + (l >> 2)];
                bh[0] = __float_as_uint(bp[0]);
                bh[1] = __float_as_uint(bp[4*72]);
                const float* bq = &Bl[(kc*8 + cq)*72 + n0*8 + (l >> 2)];
                bl2[0] = __float_as_uint(bq[0]);
                bl2[1] = __float_as_uint(bq[4*72]);
                mma8(acc[n0], ah, bh);
                mma8(acc[n0], ah, bl2);
                mma8(acc[n0], al, bh);
            }
        }
    }

    // Epilogue: lane covers rows r0, r0+8; cols n0*8 + 2*cq, +1.
    int rg1 = m0 + r0, rg2 = rg1 + 8;
    if (mode == 0) {
        float* G = (which == 0) ? g_Q : (which == 1) ? g_K : g_V;
        int b1 = rg1 >> 11, s1 = rg1 & 2047;
        int b2 = rg2 >> 11, s2 = rg2 & 2047;
        float* p1 = G + ((size_t)(b1*HH + hn)*SS + s1) * DK;
        float* p2 = G + ((size_t)(b2*HH + hn)*SS + s2) * DK;
        #pragma unroll
        for (int n0 = 0; n0 < 8; n0++) {
            int cn = n0*8 + 2*cq;
            *(float2*)&p1[cn] = make_float2(acc[n0][0], acc[n0][1]);
            *(float2*)&p2[cn] = make_float2(acc[n0][2], acc[n0][3]);
        }
    } else {
        #pragma unroll
        for (int n0 = 0; n0 < 8; n0++) {
            int cn = hn*64 + n0*8 + 2*cq;
            *(float2*)&outp[(size_t)rg1 * EE + cn] = make_float2(acc[n0][0], acc[n0][1]);
            *(float2*)&outp[(size_t)rg2 * EE + cn] = make_float2(acc[n0][2], acc[n0][3]);
        }
    }
}

// ---------------------------------------------------------------------------
// Flash attention, 3xTF32 tensor cores. grid=(S/64, H, B), block=128 (4 warps).
// Warp w owns query rows [16w, 16w+16). Q hi/lo fragments in registers
// (pre-scaled by 1/8). Per 64-key tile: QK^T (3x mma) -> fp32 scores in Ph;
// masked online softmax (mask from gmem); P -> hi/lo in Ph/Pl;
// PV (3x mma) into register accumulators with per-row rescale.
// ---------------------------------------------------------------------------
#define FLASH_SMEM ((4*64*68 + 2*64*72 + 3*64) * 4)

__global__ __launch_bounds__(128) void flash_kernel(const int* __restrict__ mask)
{
    extern __shared__ char smraw[];
    float* Kh = (float*)smraw;            // [64][68]
    float* Kl = Kh + 64*68;               // [64][68]
    float* Ph = Kl + 64*68;               // [64][68] scores fp32 / P hi
    float* Pl = Ph + 64*68;               // [64][68] P lo
    float* Vh = Pl + 64*68;               // [64][72]
    float* Vl = Vh + 64*72;               // [64][72]
    float* m_s    = Vl + 64*72;           // [64]
    float* l_s    = m_s + 64;             // [64]
    float* corr_s = l_s + 64;             // [64]

    int qt = blockIdx.x, h = blockIdx.y, b = blockIdx.z;
    int t = threadIdx.x, w = t >> 5, l = t & 31;

    const float* Qp = g_Q + ((size_t)(b*HH + h)*SS + qt*64) * DK;
    const float* Kp = g_K + (size_t)(b*HH + h) * SS * DK;
    const float* Vp = g_V + (size_t)(b*HH + h) * SS * DK;
    const int*   Mp = mask + ((size_t)b*SS + qt*64) * SS;

    int r0 = 16*w + (l >> 2);
    int cq = l & 3;

    // Stage Q (x 1/8) hi into Ph, lo into Pl; then pull fragments to regs.
    #pragma unroll
    for (int i = 0; i < 8; i++) {
        int idx = t + i * 128;
        int r = idx >> 4, c4 = idx & 15;
        float4 v = *(const float4*)&Qp[r*DK + c4*4];
        float xs[4] = {v.x * 0.125f, v.y * 0.125f, v.z * 0.125f, v.w * 0.125f};
        float* dh = &Ph[r*68 + c4*4];
        float* dl = &Pl[r*68 + c4*4];
        #pragma unroll
        for (int j = 0; j < 4; j++) {
            float hh = f2tf(xs[j]);
            dh[j] = hh;
            dl[j] = f2tf(xs[j] - hh);
        }
    }
    if (t < 64) { m_s[t] = -INFINITY; l_s[t] = 0.f; }
    __syncthreads();

    unsigned qfh[8][4], qfl[8][4];
    #pragma unroll
    for (int kc = 0; kc < 8; kc++) {
        const float* ap = &Ph[r0*68 + kc*8 + cq];
        qfh[kc][0] = __float_as_uint(ap[0]);
        qfh[kc][1] = __float_as_uint(ap[8*68]);
        qfh[kc][2] = __float_as_uint(ap[4]);
        qfh[kc][3] = __float_as_uint(ap[8*68 + 4]);
        const float* aq = &Pl[r0*68 + kc*8 + cq];
        qfl[kc][0] = __float_as_uint(aq[0]);
        qfl[kc][1] = __float_as_uint(aq[8*68]);
        qfl[kc][2] = __float_as_uint(aq[4]);
        qfl[kc][3] = __float_as_uint(aq[8*68 + 4]);
    }

    float acc[8][4] = {};

    for (int kt = 0; kt < SS/64; kt++) {
        __syncthreads();
        const float* Kt = Kp + (size_t)kt * 64 * DK;
        const float* Vt = Vp + (size_t)kt * 64 * DK;
        #pragma unroll
        for (int i = 0; i < 8; i++) {
            int idx = t + i * 128;
            int r = idx >> 4, c4 = idx & 15;
            float4 kv = *(const float4*)&Kt[r*DK + c4*4];
            float* kh = &Kh[r*68 + c4*4];
            float* kl = &Kl[r*68 + c4*4];
            float hh;
            hh = f2tf(kv.x); kh[0] = hh; kl[0] = f2tf(kv.x - hh);
            hh = f2tf(kv.y); kh[1] = hh; kl[1] = f2tf(kv.y - hh);
            hh = f2tf(kv.z); kh[2] = hh; kl[2] = f2tf(kv.z - hh);
            hh = f2tf(kv.w); kh[3] = hh; kl[3] = f2tf(kv.w - hh);
            float4 vv = *(const float4*)&Vt[r*DK + c4*4];
            float* vh = &Vh[r*72 + c4*4];
            float* vl = &Vl[r*72 + c4*4];
            hh = f2tf(vv.x); vh[0] = hh; vl[0] = f2tf(vv.x - hh);
            hh = f2tf(vv.y); vh[1] = hh; vl[1] = f2tf(vv.y - hh);
            hh = f2tf(vv.z); vh[2] = hh; vl[2] = f2tf(vv.z - hh);
            hh = f2tf(vv.w); vh[3] = hh; vl[3] = f2tf(vv.w - hh);
        }
        __syncthreads();

        // ---- QK^T (3x tf32) ----
        float sacc[8][4] = {};
        #pragma unroll
        for (int kc = 0; kc < 8; kc++) {
            #pragma unroll
            for (int n0 = 0; n0 < 8; n0++) {
                unsigned bh[2], bl2[2];
                const float* bp = &Kh[(n0*8 + (l >> 2))*68 + kc*8 + cq];
                bh[0] = __float_as_uint(bp[0]);
                bh[1] = __float_as_uint(bp[4]);
                const float* bq = &Kl[(n0*8 + (l >> 2))*68 + kc*8 + cq];
                bl2[0] = __float_as_uint(bq[0]);
                bl2[1] = __float_as_uint(bq[4]);
                mma8(sacc[n0], qfh[kc], bh);
                mma8(sacc[n0], qfh[kc], bl2);
                mma8(sacc[n0], qfl[kc], bh);
            }
        }
        #pragma unroll
        for (int n0 = 0; n0 < 8; n0++) {
            int cc = n0*8 + 2*cq;
            *(float2*)&Ph[r0*68 + cc]     = make_float2(sacc[n0][0], sacc[n0][1]);
            *(float2*)&Ph[(r0+8)*68 + cc] = make_float2(sacc[n0][2], sacc[n0][3]);
        }
        __syncwarp();

        // ---- masked online softmax (lane pair per row: 32 cols each) ----
        {
            int row = 16*w + (l >> 1);
            int j0 = (l & 1) * 32;
            const int* Mr = Mp + (size_t)row * SS + kt*64 + j0;
            float s[32];
            #pragma unroll
            for (int i = 0; i < 8; i++) {
                float4 v = *(const float4*)&Ph[row*68 + j0 + i*4];
                s[i*4] = v.x; s[i*4+1] = v.y; s[i*4+2] = v.z; s[i*4+3] = v.w;
            }
            #pragma unroll
            for (int i = 0; i < 8; i++) {
                int4 mm = *(const int4*)&Mr[i*4];
                s[i*4]   = mm.x ? s[i*4]   : -1e9f;
                s[i*4+1] = mm.y ? s[i*4+1] : -1e9f;
                s[i*4+2] = mm.z ? s[i*4+2] : -1e9f;
                s[i*4+3] = mm.w ? s[i*4+3] : -1e9f;
            }
            float mx = -INFINITY;
            #pragma unroll
            for (int j = 0; j < 32; j++) mx = fmaxf(mx, s[j]);
            mx = fmaxf(mx, __shfl_xor_sync(0xffffffffu, mx, 1));
            float mold = m_s[row];
            float mnew = fmaxf(mold, mx);
            float corr = __expf(mold - mnew);   // 0 on first tile (mold=-inf)
            float ls = 0.f;
            #pragma unroll
            for (int j = 0; j < 32; j++) {
                float p = __expf(s[j] - mnew);
                s[j] = p;
                ls += p;
            }
            ls += __shfl_xor_sync(0xffffffffu, ls, 1);
            #pragma unroll
            for (int i = 0; i < 8; i++) {
                float4 vh4, vl4;
                float hh;
                hh = f2tf(s[i*4]);   vh4.x = hh; vl4.x = f2tf(s[i*4]   - hh);
                hh = f2tf(s[i*4+1]); vh4.y = hh; vl4.y = f2tf(s[i*4+1] - hh);
                hh = f2tf(s[i*4+2]); vh4.z = hh; vl4.z = f2tf(s[i*4+2] - hh);
                hh = f2tf(s[i*4+3]); vh4.w = hh; vl4.w = f2tf(s[i*4+3] - hh);
                *(float4*)&Ph[row*68 + j0 + i*4] = vh4;
                *(float4*)&Pl[row*68 + j0 + i*4] = vl4;
            }
            m_s[row] = mnew;
            l_s[row] = l_s[row] * corr + ls;
            corr_s[row] = corr;
        }
        __syncwarp();

        // ---- PV (3x tf32) ----
        float cr1 = corr_s[r0];
        float cr2 = corr_s[r0 + 8];
        #pragma unroll
        for (int n0 = 0; n0 < 8; n0++) {
            acc[n0][0] *= cr1; acc[n0][1] *= cr1;
            acc[n0][2] *= cr2; acc[n0][3] *= cr2;
        }
        #pragma unroll
        for (int kc = 0; kc < 8; kc++) {
            unsigned ah[4], al[4];
            const float* ap = &Ph[r0*68 + kc*8 + cq];
            ah[0] = __float_as_uint(ap[0]);
            ah[1] = __float_as_uint(ap[8*68]);
            ah[2] = __float_as_uint(ap[4]);
            ah[3] = __float_as_uint(ap[8*68 + 4]);
            const float* aq = &Pl[r0*68 + kc*8 + cq];
            al[0] = __float_as_uint(aq[0]);
            al[1] = __float_as_uint(aq[8*68]);
            al[2] = __float_as_uint(aq[4]);
            al[3] = __float_as_uint(aq[8*68 + 4]);
            #pragma unroll
            for (int n0 = 0; n0 < 8; n0++) {
                unsigned bh[2], bl2[2];
                const float* bp = &Vh[(kc*8 + cq)*72 + n0*8 + (l >> 2)];
                bh[0] = __float_as_uint(bp[0]);
                bh[1] = __float_as_uint(bp[4*72]);
                const float* bq = &Vl[(kc*8 + cq)*72 + n0*8 + (l >> 2)];
                bl2[0] = __float_as_uint(bq[0]);
                bl2[1] = __float_as_uint(bq[4*72]);
                mma8(acc[n0], ah, bh);
                mma8(acc[n0], ah, bl2);
                mma8(acc[n0], al, bh);
            }
        }
    }

    __syncwarp();
    float inv1 = 1.f / l_s[r0];
    float inv2 = 1.f / l_s[r0 + 8];
    int row1 = qt*64 + r0;
    float* Cb = g_C + (size_t)b * SS * EE + (size_t)h * DK;
    #pragma unroll
    for (int n0 = 0; n0 < 8; n0++) {
        int cc = n0*8 + 2*cq;
        *(float2*)&Cb[(size_t)row1 * EE + cc] =
            make_float2(acc[n0][0]*inv1, acc[n0][1]*inv1);
        *(float2*)&Cb[(size_t)(row1+8) * EE + cc] =
            make_float2(acc[n0][2]*inv2, acc[n0][3]*inv2);
    }
}

// ---------------------------------------------------------------------------
extern "C" void kernel_launch(void* const* d_in, const int* in_sizes, int n_in,
                              void* d_out, int out_size)
{
    const float* q    = (const float*)d_in[0];
    const float* k    = (const float*)d_in[1];
    const float* v    = (const float*)d_in[2];
    const int*   mask = (const int*)  d_in[3];
    const float* Wq   = (const float*)d_in[4];
    const float* Wk   = (const float*)d_in[5];
    const float* Wv   = (const float*)d_in[6];
    const float* W    = (const float*)d_in[7];
    float* out = (float*)d_out;

    cudaFuncSetAttribute(flash_kernel,
                         cudaFuncAttributeMaxDynamicSharedMemorySize, FLASH_SMEM);

    // QKV projections (3xTF32 tensor cores)
    gemm_kernel<<<dim3((BB*SS)/64, HH, 3), 128>>>(q, k, v, Wq, Wk, Wv, nullptr, nullptr, 0);

    // Flash attention (3xTF32 tensor cores)
    flash_kernel<<<dim3(SS/64, HH, BB), 128, FLASH_SMEM>>>(mask);

    // Output projection (3xTF32 tensor cores)
    gemm_kernel<<<dim3((BB*SS)/64, EE/64, 1), 128>>>(nullptr, nullptr, nullptr,
                                                     nullptr, nullptr, nullptr, W, out, 1);
}

// round 6
// speedup vs baseline: 5.7229x; 1.5541x over previous
#include <cuda_runtime.h>
#include <cuda_bf16.h>
#include <math.h>

#define BB 2
#define SS 2048
#define EE 768
#define HH 12
#define DK 64

// Scratch (allocation-free: __device__ globals)
__device__ float g_Q[BB*HH*SS*DK];   // [B,H,S,Dk]
__device__ float g_K[BB*HH*SS*DK];
__device__ float g_V[BB*HH*SS*DK];
__device__ float g_C[BB*SS*EE];      // concat [B,S,H*Dk]

// Split two floats into packed bf16x2 hi and lo words (lo = residual).
__device__ __forceinline__ void split2(float x0, float x1, unsigned& hi, unsigned& lo) {
    __nv_bfloat162 h2 = __floats2bfloat162_rn(x0, x1);
    float h0 = __bfloat162float(__low2bfloat16(h2));
    float h1 = __bfloat162float(__high2bfloat16(h2));
    __nv_bfloat162 l2 = __floats2bfloat162_rn(x0 - h0, x1 - h1);
    hi = *reinterpret_cast<unsigned*>(&h2);
    lo = *reinterpret_cast<unsigned*>(&l2);
}

// D += A*B, m16n8k16 bf16, A row-major, B col-major, f32 accumulate.
__device__ __forceinline__ void mma16(float c[4], const unsigned a[4], const unsigned b[2]) {
    asm volatile(
        "mma.sync.aligned.m16n8k16.row.col.f32.bf16.bf16.f32 "
        "{%0,%1,%2,%3},{%4,%5,%6,%7},{%8,%9},{%0,%1,%2,%3};"
        : "+f"(c[0]), "+f"(c[1]), "+f"(c[2]), "+f"(c[3])
        : "r"(a[0]), "r"(a[1]), "r"(a[2]), "r"(a[3]), "r"(b[0]), "r"(b[1]));
}

// ---------------------------------------------------------------------------
// 3xBF16 GEMM, 64x64 block tile, BK=32, 128 threads (4 warps x 16 rows).
// Tiles stored as packed bf16x2 words along K, word stride 20 (conflict-free
// fragment reads: 20 ≡ 4 mod 32 in words for 8 rows x 4 lanes).
// mode 0: QKV projections. grid=(M/64, H, 3).
// mode 1: out projection. grid=(M/64, EE/64, 1).
// ---------------------------------------------------------------------------
#define GW 20

__global__ __launch_bounds__(128) void gemm_kernel(
    const float* __restrict__ Xq, const float* __restrict__ Xk, const float* __restrict__ Xv,
    const float* __restrict__ Wq, const float* __restrict__ Wk, const float* __restrict__ Wv,
    const float* __restrict__ Wo, float* __restrict__ outp, int mode)
{
    __shared__ unsigned Ah[64*GW], Al[64*GW];   // [row][k2]
    __shared__ unsigned Bh[64*GW], Bl[64*GW];   // [n][k2]

    int bx = blockIdx.x, hn = blockIdx.y, which = blockIdx.z;
    int t = threadIdx.x, w = t >> 5, l = t & 31;
    int g = l >> 2, t4 = l & 3;
    int m0 = bx * 64;

    const float* A;
    const float* Bw;
    int ldb;
    if (mode == 0) {
        A = (which == 0) ? Xq : (which == 1) ? Xk : Xv;
        const float* Ws = (which == 0) ? Wq : (which == 1) ? Wk : Wv;
        Bw = Ws + (size_t)hn * EE * DK;
        ldb = DK;
    } else {
        A = g_C;
        Bw = Wo + hn * 64;
        ldb = EE;
    }

    float acc[8][4] = {};
    int r0 = 16*w + g;   // fragment row base

    for (int k0 = 0; k0 < EE; k0 += 32) {
        __syncthreads();
        // A tile: 64 rows x 16 k-words
        #pragma unroll
        for (int i = 0; i < 8; i++) {
            int idx = t + i * 128;
            int r = idx >> 4, k2 = idx & 15;
            float2 x = *(const float2*)&A[(size_t)(m0 + r) * EE + k0 + 2*k2];
            split2(x.x, x.y, Ah[r*GW + k2], Al[r*GW + k2]);
        }
        // B tile: [n][k2] (transposed pack from K-major gmem)
        #pragma unroll
        for (int i = 0; i < 8; i++) {
            int idx = t + i * 128;
            int n = idx & 63, k2 = idx >> 6;
            float x0 = Bw[(size_t)(k0 + 2*k2)     * ldb + n];
            float x1 = Bw[(size_t)(k0 + 2*k2 + 1) * ldb + n];
            split2(x0, x1, Bh[n*GW + k2], Bl[n*GW + k2]);
        }
        __syncthreads();

        #pragma unroll
        for (int kc = 0; kc < 2; kc++) {
            int kw = kc*8 + t4;
            int ra = r0*GW + kw;
            unsigned ah[4] = {Ah[ra], Ah[ra + 8*GW], Ah[ra + 4], Ah[ra + 8*GW + 4]};
            unsigned al[4] = {Al[ra], Al[ra + 8*GW], Al[ra + 4], Al[ra + 8*GW + 4]};
            #pragma unroll
            for (int n0 = 0; n0 < 8; n0++) {
                int rb = (n0*8 + g)*GW + kw;
                unsigned bh2[2] = {Bh[rb], Bh[rb + 4]};
                unsigned bl2[2] = {Bl[rb], Bl[rb + 4]};
                mma16(acc[n0], ah, bh2);
                mma16(acc[n0], ah, bl2);
                mma16(acc[n0], al, bh2);
            }
        }
    }

    // Epilogue: lane covers rows r0, r0+8; cols n0*8 + 2*t4, +1.
    int rg1 = m0 + r0, rg2 = rg1 + 8;
    if (mode == 0) {
        float* G = (which == 0) ? g_Q : (which == 1) ? g_K : g_V;
        int b1 = rg1 >> 11, s1 = rg1 & 2047;
        int b2 = rg2 >> 11, s2 = rg2 & 2047;
        float* p1 = G + ((size_t)(b1*HH + hn)*SS + s1) * DK;
        float* p2 = G + ((size_t)(b2*HH + hn)*SS + s2) * DK;
        #pragma unroll
        for (int n0 = 0; n0 < 8; n0++) {
            int cn = n0*8 + 2*t4;
            *(float2*)&p1[cn] = make_float2(acc[n0][0], acc[n0][1]);
            *(float2*)&p2[cn] = make_float2(acc[n0][2], acc[n0][3]);
        }
    } else {
        #pragma unroll
        for (int n0 = 0; n0 < 8; n0++) {
            int cn = hn*64 + n0*8 + 2*t4;
            *(float2*)&outp[(size_t)rg1 * EE + cn] = make_float2(acc[n0][0], acc[n0][1]);
            *(float2*)&outp[(size_t)rg2 * EE + cn] = make_float2(acc[n0][2], acc[n0][3]);
        }
    }
}

// ---------------------------------------------------------------------------
// Flash attention, 3xBF16 tensor cores. grid=(S/64, H, B), block=128 (4 warps).
// Warp w owns query rows [16w, 16w+16). Q hi/lo fragments in registers
// (pre-scaled by 1/8). All operand tiles packed bf16x2 along K, word stride 36
// (36 ≡ 4 mod 32 -> conflict-free fragment reads).
// ---------------------------------------------------------------------------
#define KW 36
#define FLASH_SMEM (64*68*4 + 6*64*KW*4 + 3*64*4)

__global__ __launch_bounds__(128) void flash_kernel(const int* __restrict__ mask)
{
    extern __shared__ char smraw[];
    float*    Ss  = (float*)smraw;              // [64][68] fp32 scores
    unsigned* Kh  = (unsigned*)(Ss + 64*68);    // [64 key][KW]
    unsigned* Kl  = Kh  + 64*KW;
    unsigned* Vh  = Kl  + 64*KW;                // [64 dk][KW] (key-packed)
    unsigned* Vl  = Vh  + 64*KW;
    unsigned* P2h = Vl  + 64*KW;                // [64 q][KW] (Q staging, then P)
    unsigned* P2l = P2h + 64*KW;
    float* m_s    = (float*)(P2l + 64*KW);      // [64]
    float* l_s    = m_s + 64;
    float* corr_s = l_s + 64;

    int qt = blockIdx.x, h = blockIdx.y, b = blockIdx.z;
    int t = threadIdx.x, w = t >> 5, l = t & 31;
    int g = l >> 2, t4 = l & 3;
    int r0 = 16*w + g;

    const float* Qp = g_Q + ((size_t)(b*HH + h)*SS + qt*64) * DK;
    const float* Kp = g_K + (size_t)(b*HH + h) * SS * DK;
    const float* Vp = g_V + (size_t)(b*HH + h) * SS * DK;
    const int*   Mp = mask + ((size_t)b*SS + qt*64) * SS;

    // Stage Q (x 1/8) hi/lo packed into P2h/P2l, then pull fragments to regs.
    #pragma unroll
    for (int i = 0; i < 16; i++) {
        int idx = t + i * 128;
        int r = idx >> 5, k2 = idx & 31;
        float2 x = *(const float2*)&Qp[r*DK + 2*k2];
        split2(x.x * 0.125f, x.y * 0.125f, P2h[r*KW + k2], P2l[r*KW + k2]);
    }
    if (t < 64) { m_s[t] = -INFINITY; l_s[t] = 0.f; }
    __syncthreads();

    unsigned qfh[4][4], qfl[4][4];
    #pragma unroll
    for (int kc = 0; kc < 4; kc++) {
        int ra = r0*KW + kc*8 + t4;
        qfh[kc][0] = P2h[ra];     qfh[kc][1] = P2h[ra + 8*KW];
        qfh[kc][2] = P2h[ra + 4]; qfh[kc][3] = P2h[ra + 8*KW + 4];
        qfl[kc][0] = P2l[ra];     qfl[kc][1] = P2l[ra + 8*KW];
        qfl[kc][2] = P2l[ra + 4]; qfl[kc][3] = P2l[ra + 8*KW + 4];
    }

    float acc[8][4] = {};

    for (int kt = 0; kt < SS/64; kt++) {
        __syncthreads();
        const float* Kt = Kp + (size_t)kt * 64 * DK;
        const float* Vt = Vp + (size_t)kt * 64 * DK;
        // K tile: [key][dk2], straight pack
        #pragma unroll
        for (int i = 0; i < 16; i++) {
            int idx = t + i * 128;
            int r = idx >> 5, k2 = idx & 31;
            float2 x = *(const float2*)&Kt[r*DK + 2*k2];
            split2(x.x, x.y, Kh[r*KW + k2], Kl[r*KW + k2]);
        }
        // V tile transposed: [dk][key2], pack across key pairs
        #pragma unroll
        for (int i = 0; i < 16; i++) {
            int idx = t + i * 128;
            int d = idx & 63, key2 = idx >> 6;
            float x0 = Vt[(2*key2)     * DK + d];
            float x1 = Vt[(2*key2 + 1) * DK + d];
            split2(x0, x1, Vh[d*KW + key2], Vl[d*KW + key2]);
        }
        __syncthreads();

        // ---- QK^T (3x bf16) ----
        float sacc[8][4] = {};
        #pragma unroll
        for (int kc = 0; kc < 4; kc++) {
            #pragma unroll
            for (int n0 = 0; n0 < 8; n0++) {
                int rb = (n0*8 + g)*KW + kc*8 + t4;
                unsigned bh2[2] = {Kh[rb], Kh[rb + 4]};
                unsigned bl2[2] = {Kl[rb], Kl[rb + 4]};
                mma16(sacc[n0], qfh[kc], bh2);
                mma16(sacc[n0], qfh[kc], bl2);
                mma16(sacc[n0], qfl[kc], bh2);
            }
        }
        #pragma unroll
        for (int n0 = 0; n0 < 8; n0++) {
            int cc = n0*8 + 2*t4;
            *(float2*)&Ss[r0*68 + cc]     = make_float2(sacc[n0][0], sacc[n0][1]);
            *(float2*)&Ss[(r0+8)*68 + cc] = make_float2(sacc[n0][2], sacc[n0][3]);
        }
        __syncwarp();

        // ---- masked online softmax (lane pair per row: 32 cols each) ----
        {
            int row = 16*w + (l >> 1);
            int j0 = (l & 1) * 32;
            const int* Mr = Mp + (size_t)row * SS + kt*64 + j0;
            float s[32];
            #pragma unroll
            for (int i = 0; i < 8; i++) {
                float4 v = *(const float4*)&Ss[row*68 + j0 + i*4];
                s[i*4] = v.x; s[i*4+1] = v.y; s[i*4+2] = v.z; s[i*4+3] = v.w;
            }
            #pragma unroll
            for (int i = 0; i < 8; i++) {
                int4 mm = *(const int4*)&Mr[i*4];
                s[i*4]   = mm.x ? s[i*4]   : -1e9f;
                s[i*4+1] = mm.y ? s[i*4+1] : -1e9f;
                s[i*4+2] = mm.z ? s[i*4+2] : -1e9f;
                s[i*4+3] = mm.w ? s[i*4+3] : -1e9f;
            }
            float mx = -INFINITY;
            #pragma unroll
            for (int j = 0; j < 32; j++) mx = fmaxf(mx, s[j]);
            mx = fmaxf(mx, __shfl_xor_sync(0xffffffffu, mx, 1));
            float mold = m_s[row];
            float mnew = fmaxf(mold, mx);
            float corr = __expf(mold - mnew);   // 0 on first tile (mold=-inf)
            float ls = 0.f;
            #pragma unroll
            for (int j = 0; j < 32; j++) {
                float p = __expf(s[j] - mnew);
                s[j] = p;
                ls += p;
            }
            ls += __shfl_xor_sync(0xffffffffu, ls, 1);
            int c0 = (l & 1) * 16;
            #pragma unroll
            for (int i = 0; i < 16; i++)
                split2(s[2*i], s[2*i+1], P2h[row*KW + c0 + i], P2l[row*KW + c0 + i]);
            m_s[row] = mnew;
            l_s[row] = l_s[row] * corr + ls;
            corr_s[row] = corr;
        }
        __syncwarp();

        // ---- PV (3x bf16) ----
        float cr1 = corr_s[r0];
        float cr2 = corr_s[r0 + 8];
        #pragma unroll
        for (int n0 = 0; n0 < 8; n0++) {
            acc[n0][0] *= cr1; acc[n0][1] *= cr1;
            acc[n0][2] *= cr2; acc[n0][3] *= cr2;
        }
        #pragma unroll
        for (int kc = 0; kc < 4; kc++) {
            int ra = r0*KW + kc*8 + t4;
            unsigned ah[4] = {P2h[ra], P2h[ra + 8*KW], P2h[ra + 4], P2h[ra + 8*KW + 4]};
            unsigned al[4] = {P2l[ra], P2l[ra + 8*KW], P2l[ra + 4], P2l[ra + 8*KW + 4]};
            #pragma unroll
            for (int n0 = 0; n0 < 8; n0++) {
                int rb = (n0*8 + g)*KW + kc*8 + t4;
                unsigned bh2[2] = {Vh[rb], Vh[rb + 4]};
                unsigned bl2[2] = {Vl[rb], Vl[rb + 4]};
                mma16(acc[n0], ah, bh2);
                mma16(acc[n0], ah, bl2);
                mma16(acc[n0], al, bh2);
            }
        }
    }

    __syncwarp();
    float inv1 = 1.f / l_s[r0];
    float inv2 = 1.f / l_s[r0 + 8];
    int row1 = qt*64 + r0;
    float* Cb = g_C + (size_t)b * SS * EE + (size_t)h * DK;
    #pragma unroll
    for (int n0 = 0; n0 < 8; n0++) {
        int cc = n0*8 + 2*t4;
        *(float2*)&Cb[(size_t)row1 * EE + cc] =
            make_float2(acc[n0][0]*inv1, acc[n0][1]*inv1);
        *(float2*)&Cb[(size_t)(row1+8) * EE + cc] =
            make_float2(acc[n0][2]*inv2, acc[n0][3]*inv2);
    }
}

// ---------------------------------------------------------------------------
extern "C" void kernel_launch(void* const* d_in, const int* in_sizes, int n_in,
                              void* d_out, int out_size)
{
    const float* q    = (const float*)d_in[0];
    const float* k    = (const float*)d_in[1];
    const float* v    = (const float*)d_in[2];
    const int*   mask = (const int*)  d_in[3];
    const float* Wq   = (const float*)d_in[4];
    const float* Wk   = (const float*)d_in[5];
    const float* Wv   = (const float*)d_in[6];
    const float* W    = (const float*)d_in[7];
    float* out = (float*)d_out;

    cudaFuncSetAttribute(flash_kernel,
                         cudaFuncAttributeMaxDynamicSharedMemorySize, FLASH_SMEM);

    // QKV projections (3xBF16 tensor cores)
    gemm_kernel<<<dim3((BB*SS)/64, HH, 3), 128>>>(q, k, v, Wq, Wk, Wv, nullptr, nullptr, 0);

    // Flash attention (3xBF16 tensor cores)
    flash_kernel<<<dim3(SS/64, HH, BB), 128, FLASH_SMEM>>>(mask);

    // Output projection (3xBF16 tensor cores)
    gemm_kernel<<<dim3((BB*SS)/64, EE/64, 1), 128>>>(nullptr, nullptr, nullptr,
                                                     nullptr, nullptr, nullptr, W, out, 1);
}